// round 3
// baseline (speedup 1.0000x reference)
#include <cuda_runtime.h>
#include <cstdint>

// Identity: reference returns X unchanged (the torch loop's writes are dead).
// Fastest correct kernel = saturating HBM copy d_in[0] -> d_out.
// 8192*4096 fp32 = 2^25 floats = 2^23 float4 -> exact-fit grid, no tail.

__global__ void copy_f4_kernel(const float4* __restrict__ src,
                               float4* __restrict__ dst,
                               long long n4) {
    long long i = (long long)blockIdx.x * blockDim.x + threadIdx.x;
    long long stride = (long long)gridDim.x * blockDim.x;
    for (; i < n4; i += stride) {
        dst[i] = src[i];
    }
}

// Scalar fallback for any non-16B-divisible tail (not expected for this shape).
__global__ void copy_f1_kernel(const float* __restrict__ src,
                               float* __restrict__ dst,
                               long long n) {
    long long i = (long long)blockIdx.x * blockDim.x + threadIdx.x;
    long long stride = (long long)gridDim.x * blockDim.x;
    for (; i < n; i += stride) {
        dst[i] = src[i];
    }
}

extern "C" void kernel_launch(void* const* d_in, const int* in_sizes, int n_in,
                              void* d_out, int out_size) {
    const float* x = (const float*)d_in[0];
    float* out = (float*)d_out;
    long long n = (long long)out_size;   // 33,554,432 floats expected

    long long n4 = n >> 2;               // floats in vector path
    long long rem = n - (n4 << 2);

    if (n4 > 0) {
        const int threads = 256;
        // Exact-fit grid for the expected shape (8M float4 / 256 = 32768 blocks).
        long long blocks_ll = (n4 + threads - 1) / threads;
        int blocks = (blocks_ll > 1048576LL) ? 1048576 : (int)blocks_ll;
        copy_f4_kernel<<<blocks, threads>>>((const float4*)x, (float4*)out, n4);
    }
    if (rem > 0) {
        copy_f1_kernel<<<1, 256>>>(x + (n4 << 2), out + (n4 << 2), n);
        // note: kernel grid-strides from its own start; launch covers tail only
    }
}

// round 4
// speedup vs baseline: 1.0769x; 1.0769x over previous
#include <cuda_runtime.h>
#include <cstdint>

// Identity op: reference output == input X (torch loop writes are dead code).
// Pure HBM copy, tuned: 4x float4 per thread (front-batched loads -> MLP=4),
// streaming cache hints (.cs) since there is zero reuse and the working set
// (2 x 128 MiB) exceeds L2.

constexpr int VPT = 4;  // float4 per thread (64 bytes)

__global__ void copy_f4x4_kernel(const float4* __restrict__ src,
                                 float4* __restrict__ dst,
                                 long long n4) {
    // Block-contiguous chunk: block b owns [b*blockDim*VPT, ...) with
    // thread-interleaved (coalesced) access inside each sub-stripe.
    long long base = (long long)blockIdx.x * (blockDim.x * VPT) + threadIdx.x;

    float4 v[VPT];
    // Front-batch all loads: 4 independent LDG.128 in flight per thread.
    #pragma unroll
    for (int j = 0; j < VPT; j++) {
        long long i = base + (long long)j * blockDim.x;
        if (i < n4) v[j] = __ldcs(src + i);
    }
    #pragma unroll
    for (int j = 0; j < VPT; j++) {
        long long i = base + (long long)j * blockDim.x;
        if (i < n4) __stcs(dst + i, v[j]);
    }
}

// Scalar tail fallback (not expected for this shape: 2^25 floats).
__global__ void copy_f1_kernel(const float* __restrict__ src,
                               float* __restrict__ dst,
                               long long n) {
    long long i = (long long)blockIdx.x * blockDim.x + threadIdx.x;
    if (i < n) dst[i] = src[i];
}

extern "C" void kernel_launch(void* const* d_in, const int* in_sizes, int n_in,
                              void* d_out, int out_size) {
    const float* x = (const float*)d_in[0];
    float* out = (float*)d_out;
    long long n = (long long)out_size;   // 33,554,432 floats expected

    long long n4 = n >> 2;
    long long rem = n - (n4 << 2);

    if (n4 > 0) {
        const int threads = 256;
        const long long per_block = (long long)threads * VPT;  // 1024 float4
        long long blocks_ll = (n4 + per_block - 1) / per_block;  // 8192 expected
        int blocks = (blocks_ll > 1048576LL) ? 1048576 : (int)blocks_ll;
        copy_f4x4_kernel<<<blocks, threads>>>((const float4*)x, (float4*)out, n4);
    }
    if (rem > 0) {
        const float* s = x + (n4 << 2);
        float* d = out + (n4 << 2);
        copy_f1_kernel<<<1, 256>>>(s, d, rem);
    }
}